// round 15
// baseline (speedup 1.0000x reference)
#include <cuda_runtime.h>

// GPUBiasingMultiModel R15: R14 (best: 34.0us) with a slimmed store loop:
//   1. packed f32x2 adds (hoisted aw = alpha*w; per hyp: mov.b64 + 4 FADD2
//      instead of 8 FMA),
//   2. nx default registers live OUTSIDE the loop; patched-then-restored only
//      on the rare gated path (kills 8 MOVs/hyp),
//   3. per-hyp output offset precomputed in Phase A (one LDS.64 replaces the
//      64-bit multiply chain); per-thread slot bitmap gates the patch scan.
// Everything else (shape, buckets, slow path) identical to R14.

#define MAXLVL 4
#define TILE   1024   // labels per tile (8 floats/thread @128 thr)
#define CHUNK  128    // hyp indices per block (== blockDim)
#define NCAP   32     // hyp slots with fast-path buckets
#define BCAP   8      // entries per (hyp, warp) bucket

#define ADD_F32X2(out, a, b) \
    asm("add.rn.f32x2 %0, %1, %2;" : "=l"(out) : "l"(a), "l"(b))
#define PACK_F32X2(out, lo, hi) \
    asm("mov.b64 %0, {%1, %2};" : "=l"(out) : "r"(lo), "r"(hi))

union F4 { float4 f; unsigned long long u[2]; };

__device__ __forceinline__ void setc(float4& v, int c, float x) {
    v.x = (c == 0) ? x : v.x;
    v.y = (c == 1) ? x : v.y;
    v.z = (c == 2) ? x : v.z;
    v.w = (c == 3) ? x : v.w;
}

__global__ void __launch_bounds__(128) fused_kernel(
    const float* __restrict__ arc_w, const int* __restrict__ arc_to,
    const int*   __restrict__ arc_ilab,
    const int*   __restrict__ model_ids, const float* __restrict__ alpha,
    const int*   __restrict__ states,
    const int*   __restrict__ bo_to, const float* __restrict__ bo_w,
    const float* __restrict__ final_w, const int* __restrict__ eos_ptr,
    float* __restrict__ out_scores, float* __restrict__ out_next,
    int V, int per_model, int B, int S, int K)
{
    const int tile = blockIdx.x;
    const int m    = blockIdx.y;
    const int h0   = blockIdx.z * CHUNK;
    const int t    = threadIdx.x;
    const int vlo  = tile * TILE;

    __shared__ long long sh_off[CHUNK];          // h*V + vlo (element offset)
    __shared__ float sh_c [CHUNK];
    __shared__ float sh_fw[CHUNK];
    __shared__ int   sh_s0[CHUNK];
    __shared__ int   sh_nl[CHUNK];
    __shared__ int   sh_lb[CHUNK][MAXLVL];
    __shared__ float sh_la[CHUNK][MAXLVL];
    __shared__ unsigned char sh_slow[CHUNK];
    __shared__ int      sh_cnt  [NCAP][4];
    __shared__ unsigned sh_pmask[NCAP][4];       // owner lanes per warp
    __shared__ unsigned sh_pl [NCAP][4][BCAP];   // local | key<<10
    __shared__ float    sh_ps [NCAP][4][BCAP];   // score (alpha-scaled)
    __shared__ float    sh_pn [NCAP][4][BCAP];   // next state
    __shared__ int   sh_n;
    __shared__ int   sh_anyslow;

    if (t == 0) { sh_n = 0; sh_anyslow = 0; }
    if (t < NCAP * 4) { ((int*)sh_cnt)[t] = 0; ((unsigned*)sh_pmask)[t] = 0u; }
    sh_slow[t] = 0;
    __syncthreads();

    const float a   = __ldg(alpha + m);
    const int   eos = __ldg(eos_ptr);

    // ---- Phase A: compact hyps + chain walk (one hyp per thread) ----
    {
        int h = h0 + t;
        if (h < B && __ldg(model_ids + h) == m) {
            int s = __ldg(states + h);
            const int s_first = s;
            float acc = 0.f;
            int nl = 0;
            int   lb[MAXLVL] = {0, 0, 0, 0};
            float la[MAXLVL] = {0.f, 0.f, 0.f, 0.f};
            #pragma unroll
            for (int i = 0; i < MAXLVL; i++) {
                int mm = s / S, r = s - mm * S;
                if (r == 0) break;             // reached start state
                lb[nl] = mm * per_model + V + (r - 1) * K;
                la[nl] = acc;
                nl++;
                acc += __ldg(bo_w + s);
                s = __ldg(bo_to + s);
            }
            int slot = atomicAdd(&sh_n, 1);
            sh_off[slot] = (long long)h * V + vlo;
            sh_c [slot] = acc * a;
            sh_s0[slot] = s_first;
            sh_fw[slot] = __ldg(final_w + s_first) * a;
            sh_nl[slot] = nl;
            #pragma unroll
            for (int l = 0; l < MAXLVL; l++) { sh_lb[slot][l] = lb[l]; sh_la[slot][l] = la[l]; }
            if (slot >= NCAP) { sh_slow[slot] = 1; sh_anyslow = 1; }
        }
    }

    // ---- Tile load (independent; overlaps Phase A latency) ----
    const long long base = (long long)m * per_model + (long long)vlo;
    const float4* wsrc = (const float4*)(arc_w  + base);
    const int4*   tsrc = (const int4*)  (arc_to + base);
    float4 w0 = __ldg(wsrc + t);
    float4 w1 = __ldg(wsrc + t + 128);
    int4   i0 = __ldg(tsrc + t);
    int4   i1 = __ldg(tsrc + t + 128);
    float4 n0 = make_float4((float)i0.x, (float)i0.y, (float)i0.z, (float)i0.w);
    float4 n1 = make_float4((float)i1.x, (float)i1.y, (float)i1.z, (float)i1.w);

    __syncthreads();

    const int n = sh_n;
    if (n == 0) return;

    // ---- Phase A': build patch buckets + owner masks ----
    for (int idx = t; idx < n * MAXLVL; idx += CHUNK) {
        const int slot = idx >> 2, l = idx & 3;
        if (slot >= NCAP) continue;           // slow path covers it
        if (l >= sh_nl[slot]) continue;
        const int   lbase = sh_lb[slot][l];
        const float lacc  = sh_la[slot][l];
        int lo = 0, hi = K;                   // lower_bound(vlo)
        while (lo < hi) {
            int mid = (lo + hi) >> 1;
            if (__ldg(arc_ilab + lbase + mid) < vlo) lo = mid + 1; else hi = mid;
        }
        const int rlo = lo;
        hi = K;                               // lower_bound(vlo + TILE)
        while (lo < hi) {
            int mid = (lo + hi) >> 1;
            if (__ldg(arc_ilab + lbase + mid) < vlo + TILE) lo = mid + 1; else hi = mid;
        }
        const int rhi = lo;
        for (int j = rlo; j < rhi; j++) {
            const int il = __ldg(arc_ilab + lbase + j);
            if (il == eos) continue;          // eos column is fixed
            const int local = il - vlo;
            const int w = (local & 511) >> 7; // owning warp
            int c = atomicAdd(&sh_cnt[slot][w], 1);
            if (c < BCAP) {
                sh_pl[slot][w][c] = (unsigned)local | ((unsigned)((l << 6) | j) << 10);
                sh_ps[slot][w][c] = (lacc + __ldg(arc_w + lbase + j)) * a;
                sh_pn[slot][w][c] = (float)__ldg(arc_to + lbase + j);
                atomicOr(&sh_pmask[slot][w], 1u << ((local >> 2) & 31));
            } else {
                sh_slow[slot] = 1; sh_anyslow = 1;
            }
        }
    }
    __syncthreads();

    // ---- Store loop: packed defaults, gated patch, restore-after-store ----
    const bool eos_in   = (unsigned)(eos - vlo) < (unsigned)TILE;
    const int  eos_loc  = eos - vlo;
    const unsigned eos_mine = (eos_in && (((eos_loc & 511) >> 2) == t)) ? 1u : 0u;
    const int  warp    = t >> 5;
    const int  lanebit = t & 31;

    // Per-thread slot bitmap (slot i -> bit i), slots < NCAP only.
    unsigned mybits = 0;
    {
        const int nn = (n < NCAP) ? n : NCAP;
        for (int i = 0; i < nn; i++)
            mybits |= ((sh_pmask[i][warp] >> lanebit) & 1u) << i;
    }

    // Hoisted alpha*w (packed) and default next rows.
    F4 AW0, AW1;
    AW0.f = make_float4(a * w0.x, a * w0.y, a * w0.z, a * w0.w);
    AW1.f = make_float4(a * w1.x, a * w1.y, a * w1.z, a * w1.w);
    F4 nx0, nx1;
    nx0.f = n0; nx1.f = n1;

    float* const next_base = out_next;   // may be null

    for (int i = 0; i < n; i++) {
        const float c = sh_c[i];
        unsigned long long cc;
        PACK_F32X2(cc, __float_as_uint(c), __float_as_uint(c));
        F4 s0, s1;
        ADD_F32X2(s0.u[0], AW0.u[0], cc);
        ADD_F32X2(s0.u[1], AW0.u[1], cc);
        ADD_F32X2(s1.u[0], AW1.u[0], cc);
        ADD_F32X2(s1.u[1], AW1.u[1], cc);

        const unsigned g = ((unsigned)(i < NCAP) & (mybits >> (i & 31))) | eos_mine;
        if (g & 1u) {
            // rare: patch scores + next (next restored after the stores)
            if (i < NCAP && ((mybits >> i) & 1u)) {
                int cn = sh_cnt[i][warp];
                if (cn > BCAP) cn = BCAP;
                unsigned bk0 = 0xFFFFFFFFu, bk1 = 0xFFFFFFFFu;
                for (int e = 0; e < cn; e++) {
                    const unsigned pl = sh_pl[i][warp][e];
                    const int local = (int)(pl & 1023u);
                    if (((local & 511) >> 2) != t) continue;
                    const unsigned key = pl >> 10;
                    const int half = local >> 9;
                    const int comp = local & 3;
                    const int sh8  = comp * 8;
                    const unsigned cur = ((half ? bk1 : bk0) >> sh8) & 255u;
                    if (key < cur) {
                        const float sv = sh_ps[i][warp][e];
                        const float nv = sh_pn[i][warp][e];
                        if (!half) {
                            setc(s0.f, comp, sv); setc(nx0.f, comp, nv);
                            bk0 = (bk0 & ~(255u << sh8)) | (key << sh8);
                        } else {
                            setc(s1.f, comp, sv); setc(nx1.f, comp, nv);
                            bk1 = (bk1 & ~(255u << sh8)) | (key << sh8);
                        }
                    }
                }
            }
            if (eos_mine) {                      // eos wins all
                const int comp = eos_loc & 3;
                const float sv = sh_fw[i];
                const float nv = (float)sh_s0[i];
                if (eos_loc < 512) { setc(s0.f, comp, sv); setc(nx0.f, comp, nv); }
                else               { setc(s1.f, comp, sv); setc(nx1.f, comp, nv); }
            }
        }

        const long long off = sh_off[i];
        float4* sdst = (float4*)(out_scores + off);
        __stcs(sdst + t,       s0.f);
        __stcs(sdst + t + 128, s1.f);
        if (next_base) {
            float4* ndst = (float4*)(next_base + off);
            __stcs(ndst + t,       nx0.f);
            __stcs(ndst + t + 128, nx1.f);
        }

        if (g & 1u) { nx0.f = n0; nx1.f = n1; }  // restore defaults (rare)
    }

    // ---- Rare fallback: full-priority gmem patch for slow slots ----
    if (sh_anyslow) {
        __syncthreads();     // order default stores before patch overwrites
        for (int slot = 0; slot < n; slot++) {
            if (!sh_slow[slot]) continue;
            const int nl = sh_nl[slot];
            const long long off = sh_off[slot] - vlo;
            for (int idx = t; idx < nl * K; idx += CHUNK) {
                const int l = idx / K, j = idx - l * K;
                const int lbase = sh_lb[slot][l];
                const int il = __ldg(arc_ilab + lbase + j);
                if (il < vlo || il >= vlo + TILE) continue;
                if (il == eos) continue;
                if (j > 0 && __ldg(arc_ilab + lbase + j - 1) == il) continue;
                bool shadowed = false;
                for (int l2 = 0; l2 < l; l2++) {
                    const int b2 = sh_lb[slot][l2];
                    int lo = 0, hi = K;
                    while (lo < hi) {
                        int mid = (lo + hi) >> 1;
                        if (__ldg(arc_ilab + b2 + mid) < il) lo = mid + 1; else hi = mid;
                    }
                    if (lo < K && __ldg(arc_ilab + b2 + lo) == il) { shadowed = true; break; }
                }
                if (shadowed) continue;
                out_scores[off + il] = (sh_la[slot][l] + __ldg(arc_w + lbase + j)) * a;
                if (out_next) out_next[off + il] = (float)__ldg(arc_to + lbase + j);
            }
        }
    }
}

// ---------------- fallback: monolithic kernel (odd shapes) ----------------
#define MAXK 64
__global__ void advance_kernel(
    const float* __restrict__ arc_w, const int* __restrict__ arc_to,
    const int* __restrict__ arc_ilab,
    const int* __restrict__ bo_to, const float* __restrict__ bo_w,
    const float* __restrict__ final_w, const float* __restrict__ alpha,
    const int* __restrict__ states, const int* __restrict__ model_ids,
    const int* __restrict__ eos_ptr,
    float* __restrict__ out_scores, float* __restrict__ out_next,
    int V, int S, int K)
{
    __shared__ int       sh_ilab[MAXLVL * MAXK];
    __shared__ float     sh_w   [MAXLVL * MAXK];
    __shared__ int       sh_to  [MAXLVL * MAXK];
    __shared__ long long sh_level_base[MAXLVL];
    __shared__ float     sh_level_acc [MAXLVL];
    __shared__ int       sh_nl;
    __shared__ long long sh_start_base;
    __shared__ float     sh_start_acc;

    const int b = blockIdx.x;
    if (threadIdx.x == 0) {
        int s = states[b];
        float acc = 0.f;
        int nl = 0;
        long long start_base = -1;
        float start_acc = 0.f;
        const long long per_model = (long long)V + (long long)(S - 1) * K;
        #pragma unroll
        for (int i = 0; i < MAXLVL; i++) {
            int m = s / S, r = s - m * S;
            if (r == 0) { start_base = (long long)m * per_model; start_acc = acc; break; }
            sh_level_base[nl] = (long long)m * per_model + V + (long long)(r - 1) * K;
            sh_level_acc [nl] = acc;
            nl++;
            acc += bo_w[s];
            s = bo_to[s];
        }
        sh_nl = nl; sh_start_base = start_base; sh_start_acc = start_acc;
    }
    __syncthreads();

    const int nl = sh_nl;
    for (int idx = threadIdx.x; idx < nl * K; idx += blockDim.x) {
        int l = idx / K, j = idx - l * K;
        long long base = sh_level_base[l];
        sh_ilab[l * MAXK + j] = arc_ilab[base + j];
        sh_w   [l * MAXK + j] = arc_w   [base + j];
        sh_to  [l * MAXK + j] = arc_to  [base + j];
    }

    const int       s0      = states[b];
    const float     alpha_b = alpha[model_ids[b]];
    const int       eos     = eos_ptr[0];
    const long long sb      = sh_start_base;
    const float     sa      = sh_start_acc;
    const float     eos_sc  = final_w[s0] * alpha_b;
    const long long off     = (long long)b * V;

    for (int v = threadIdx.x; v < V; v += blockDim.x) {
        float sc = 0.f, nx = 0.f;
        if (sb >= 0) {
            sc = (sa + arc_w[sb + v]) * alpha_b;
            nx = (float)arc_to[sb + v];
        }
        if (v == eos) { sc = eos_sc; nx = (float)s0; }
        out_scores[off + v] = sc;
        if (out_next) out_next[off + v] = nx;
    }
    __syncthreads();

    for (int idx = threadIdx.x; idx < nl * K; idx += blockDim.x) {
        int l = idx / K, j = idx - l * K;
        int il = sh_ilab[l * MAXK + j];
        if (il == eos) continue;
        if (j > 0 && sh_ilab[l * MAXK + j - 1] == il) continue;
        bool shadowed = false;
        for (int l2 = 0; l2 < l; l2++) {
            const int* arr = sh_ilab + l2 * MAXK;
            int lo = 0, hi = K;
            while (lo < hi) { int mid = (lo + hi) >> 1; if (arr[mid] < il) lo = mid + 1; else hi = mid; }
            if (lo < K && arr[lo] == il) { shadowed = true; break; }
        }
        if (shadowed) continue;
        out_scores[off + il] = (sh_level_acc[l] + sh_w[l * MAXK + j]) * alpha_b;
        if (out_next) out_next[off + il] = (float)sh_to[l * MAXK + j];
    }
}

extern "C" void kernel_launch(void* const* d_in, const int* in_sizes, int n_in,
                              void* d_out, int out_size)
{
    const float* arc_w     = (const float*)d_in[0];
    const int*   arc_to    = (const int*)  d_in[1];
    const int*   arc_ilab  = (const int*)  d_in[3];
    const int*   bo_to     = (const int*)  d_in[4];
    const float* bo_w      = (const float*)d_in[5];
    const float* final_w   = (const float*)d_in[6];
    const float* alpha     = (const float*)d_in[7];
    const int*   states    = (const int*)  d_in[8];
    const int*   model_ids = (const int*)  d_in[9];
    const int*   eos       = (const int*)  d_in[10];

    const long long A        = in_sizes[0];
    const long long n_states = in_sizes[4];
    const long long M        = in_sizes[7];
    const long long B        = in_sizes[8];
    const long long S        = n_states / M;

    long long V = (long long)out_size / (2 * B);
    bool write_next = true;
    if (V * 2 * B != (long long)out_size) {
        V = (long long)out_size / B;
        write_next = false;
    }
    const long long per_model = A / M;
    const int K = (int)((per_model - V) / (S - 1));

    float* out_scores = (float*)d_out;
    float* out_next   = write_next ? out_scores + B * V : nullptr;

    if ((V % TILE) == 0 && K <= 64) {   // key packing needs j < 64
        dim3 grid((unsigned)(V / TILE), (unsigned)M, (unsigned)((B + CHUNK - 1) / CHUNK));
        fused_kernel<<<grid, CHUNK>>>(
            arc_w, arc_to, arc_ilab, model_ids, alpha, states, bo_to, bo_w,
            final_w, eos,
            out_scores, out_next, (int)V, (int)per_model, (int)B, (int)S, K);
    } else {
        advance_kernel<<<(unsigned)B, 256>>>(
            arc_w, arc_to, arc_ilab, bo_to, bo_w, final_w, alpha,
            states, model_ids, eos,
            out_scores, out_next, (int)V, (int)S, K);
    }
}